// round 11
// baseline (speedup 1.0000x reference)
#include <cuda_runtime.h>
#include <math_constants.h>

// Problem constants
#define NB 32
#define NP 576
#define ND 768
#define KP1 17
#define KF 16
#define NC 200
#define TILE_P 64
#define NTILES 9      // 576 / 64
#define T1 512
#define XSP 772       // padded x row stride (floats): conflict-free mma frags
#define DSP 26        // dist row stride

// Output layout: concatenation of (A, v_norm, logits_parts, logits_agg)
#define SZ_A (NB*KP1*NP)            // 313344
#define OFF_VN (SZ_A)
#define SZ_VN (NB*KF*ND)            // 393216
#define OFF_PARTS (OFF_VN + SZ_VN)
#define SZ_PARTS (NB*KF*NC)         // 102400
#define OFF_AGG (OFF_PARTS + SZ_PARTS)

typedef unsigned long long u64;

// v accumulator (pre-LN). Zeroed at module load; k2a re-zeroes after reading,
// so the "g_v == 0 on k1 entry" invariant holds across graph replays.
__device__ float g_v[NB*KF*ND];

// ---- f32x2 helpers (k2b only) ----------------------------------------------
__device__ __forceinline__ u64 fma2(u64 a, u64 b, u64 c) {
    u64 d; asm("fma.rn.f32x2 %0, %1, %2, %3;" : "=l"(d) : "l"(a), "l"(b), "l"(c));
    return d;
}
__device__ __forceinline__ u64 pack2(float lo, float hi) {
    u64 r; asm("mov.b64 %0, {%1,%2};" : "=l"(r) : "f"(lo), "f"(hi));
    return r;
}
__device__ __forceinline__ float2 unpack2(u64 v) {
    float2 r; asm("mov.b64 {%0,%1}, %2;" : "=f"(r.x), "=f"(r.y) : "l"(v));
    return r;
}

// ---- tf32 helpers -----------------------------------------------------------
__device__ __forceinline__ unsigned tf32_of(float x) {
    unsigned r; asm("cvt.rna.tf32.f32 %0, %1;" : "=r"(r) : "f"(x));
    return r;
}
__device__ __forceinline__ void mma_tf32(float d[4],
                                         unsigned a0, unsigned a1, unsigned a2, unsigned a3,
                                         unsigned b0, unsigned b1) {
    asm("mma.sync.aligned.m16n8k8.row.col.f32.tf32.tf32.f32 "
        "{%0,%1,%2,%3}, {%4,%5,%6,%7}, {%8,%9}, {%0,%1,%2,%3};"
        : "+f"(d[0]), "+f"(d[1]), "+f"(d[2]), "+f"(d[3])
        : "r"(a0), "r"(a1), "r"(a2), "r"(a3), "r"(b0), "r"(b1));
}

// ---------------------------------------------------------------------------
// k1: per (image, 64-patch tile) block. 512 threads, 1 block/SM (~209 KB smem).
//  Phase 1: TF32 tensor-core dists GEMM (12 warps, m16n8k8 fragments),
//           dists -> smem -> lane-parallel softmax (fp32, exact cancellation).
//  Phase 2: 384 threads own d-pairs (scalar FMA, float4 a-broadcasts);
//           128 threads write A concurrently. Epilogue: 16 float2 atomics.
// ---------------------------------------------------------------------------
__global__ __launch_bounds__(T1, 1)
void k1(const float* __restrict__ x,
        const float* __restrict__ proto,
        float* __restrict__ out)
{
    extern __shared__ float sm[];
    float* xs     = sm;                        // 64*772 floats (197.6 KB)
    float* dist_s = xs + TILE_P*XSP;           // 64*26 dot products
    float* a_c    = dist_s + TILE_P*DSP;       // 64*16 compact a (16B-aligned)
    float* a16    = a_c + TILE_P*KF;           // 64 (k=16 attention)
    float* psq    = a16 + TILE_P;              // 17

    const int t = threadIdx.x, warp = t >> 5, lane = t & 31;
    const int g = lane >> 2, tq = lane & 3;    // mma groupID / threadID_in_group
    const int tile = blockIdx.x, b = blockIdx.y;

    float4* xs4 = (float4*)xs;
    const float4* xg = (const float4*)(x + ((size_t)b*NP + (size_t)tile*TILE_P)*ND);

    // --- stage x tile into padded smem rows (coalesced 128B groups) ---
    {
        const int row = t >> 3, c = t & 7;     // 64 rows, 8 threads/row
        const float4* src = xg + row*(ND/4);
        float4* dst = xs4 + row*(XSP/4);       // XSP/4 = 193
        #pragma unroll
        for (int i = 0; i < 24; i++)
            dst[c + 8*i] = src[c + 8*i];
    }

    // --- per-block ||p_k||^2 (overlaps staging; proto L1/L2-resident) ---
    for (int k = warp; k < KP1; k += 16) {
        const float4* pk = (const float4*)(proto + (size_t)k*ND);
        float s = 0.f;
        #pragma unroll
        for (int i = 0; i < 6; i++) {
            float4 v = __ldg(&pk[lane + 32*i]);
            s += v.x*v.x + v.y*v.y + v.z*v.z + v.w*v.w;
        }
        #pragma unroll
        for (int o = 16; o; o >>= 1) s += __shfl_xor_sync(0xffffffffu, s, o);
        if (lane == 0) psq[k] = s;
    }
    __syncthreads();

    // --- Phase 1: TF32 mma dists GEMM. Warp w -> (m-tile, n-tile). ---
    if (warp < 12) {
        const int mt = warp >> 2 ? (warp / 3) : (warp / 3);  // 0..3
        const int mtt = warp / 3, nt = warp - mtt*3;         // 4 x 3 grid
        const int r0 = mtt*16 + g, r1 = r0 + 8;
        const int ng = nt*8 + g;                             // B column (proto k)
        const bool nv = (ng < KP1);
        const float* ar0 = xs + (size_t)r0*XSP;
        const float* ar1 = xs + (size_t)r1*XSP;
        const float* bp  = proto + (size_t)(nv ? ng : 0)*ND;

        float d[4] = {0.f, 0.f, 0.f, 0.f};
        #pragma unroll 4
        for (int ks = 0; ks < 96; ks++) {
            const int k0 = ks*8 + tq;
            unsigned a0 = tf32_of(ar0[k0]);
            unsigned a1 = tf32_of(ar1[k0]);
            unsigned a2 = tf32_of(ar0[k0 + 4]);
            unsigned a3 = tf32_of(ar1[k0 + 4]);
            float b0f = nv ? __ldg(bp + k0)     : 0.f;
            float b1f = nv ? __ldg(bp + k0 + 4) : 0.f;
            mma_tf32(d, a0, a1, a2, a3, tf32_of(b0f), tf32_of(b1f));
        }
        const int c0 = nt*8 + 2*tq;
        dist_s[r0*DSP + c0]     = d[0];
        dist_s[r0*DSP + c0 + 1] = d[1];
        dist_s[r1*DSP + c0]     = d[2];
        dist_s[r1*DSP + c0 + 1] = d[3];
    }
    __syncthreads();

    // --- lane-parallel softmax: softmax_k(2*xp - psq) == softmax(-dists) ---
    const int p0 = warp * 4;
    #pragma unroll
    for (int p = 0; p < 4; p++) {
        const int pl = p0 + p;
        float s = (lane < KP1) ? fmaf(2.f, dist_s[pl*DSP + lane], -psq[lane])
                               : -CUDART_INF_F;
        float m = s;
        #pragma unroll
        for (int o = 16; o; o >>= 1) m = fmaxf(m, __shfl_xor_sync(0xffffffffu, m, o));
        float e = (lane < KP1) ? __expf(s - m) : 0.f;
        float ssum = e;
        #pragma unroll
        for (int o = 16; o; o >>= 1) ssum += __shfl_xor_sync(0xffffffffu, ssum, o);
        float av = e * (1.f / ssum);
        if (lane < KF)       a_c[pl*KF + lane] = av;
        else if (lane == KF) a16[pl] = av;
    }
    __syncthreads();

    if (t >= 384) {
        // --- A output on the 128 spare threads: rows contiguous in p ---
        int tt = t - 384;
        #pragma unroll
        for (int i = tt; i < KP1*TILE_P; i += 128) {
            int k = i >> 6, p = i & 63;
            float av = (k < KF) ? a_c[p*KF + k] : a16[p];
            out[((size_t)b*KP1 + k)*NP + (size_t)tile*TILE_P + p] = av;
        }
    } else {
        // --- Phase 2: thread owns d-pair (2t, 2t+1); scalar FMA ---
        float2 vacc[KF];
        #pragma unroll
        for (int k = 0; k < KF; k++) { vacc[k].x = 0.f; vacc[k].y = 0.f; }
        const float2* xs2 = (const float2*)xs;      // row stride XSP/2 = 386
        const float4* ac4 = (const float4*)a_c;
        #pragma unroll 4
        for (int p = 0; p < TILE_P; p++) {
            float2 xv = xs2[p*(XSP/2) + t];
            float4 a0 = ac4[p*4 + 0], a1 = ac4[p*4 + 1];   // broadcast LDS.128
            float4 a2 = ac4[p*4 + 2], a3 = ac4[p*4 + 3];
            const float av[KF] = { a0.x,a0.y,a0.z,a0.w, a1.x,a1.y,a1.z,a1.w,
                                   a2.x,a2.y,a2.z,a2.w, a3.x,a3.y,a3.z,a3.w };
            #pragma unroll
            for (int k = 0; k < KF; k++) {
                vacc[k].x += av[k] * xv.x;
                vacc[k].y += av[k] * xv.y;
            }
        }
        float2* gv2 = (float2*)(g_v + (size_t)b*KF*ND);
        #pragma unroll
        for (int k = 0; k < KF; k++)
            atomicAdd(&gv2[k*(ND/2) + t], vacc[k]);   // red.global.add.v2.f32
    }
}

// ---------------------------------------------------------------------------
// k2a: LayerNorm over D for each (b,k). Applies the /P scaling.
// Re-zeroes g_v (read-then-clear) and seeds parts/agg with the bias so k2b
// can use pure red.global.add.
// ---------------------------------------------------------------------------
__global__ __launch_bounds__(256, 4)
void k2a(float* __restrict__ out,
         const float* __restrict__ gamma, const float* __restrict__ beta,
         const float* __restrict__ b_cls)
{
    const int bk = blockIdx.x;            // b*16 + k
    const int t = threadIdx.x;
    __shared__ float red[16];
    __shared__ float stats[2];
    float* gv = g_v + (size_t)bk*ND;
    const float invP = 1.f / (float)NP;

    float v[3]; float s = 0.f, sq = 0.f;
    #pragma unroll
    for (int i = 0; i < 3; i++) {
        float val = gv[t + i*256] * invP;
        gv[t + i*256] = 0.f;              // re-zero for next replay's k1
        v[i] = val; s += val; sq += val*val;
    }

    // seed logits_parts / logits_agg with the classifier bias
    if (t < NC) {
        float bcv = b_cls[t];
        out[OFF_PARTS + (size_t)bk*NC + t] = bcv;
        if ((bk & 15) == 0) out[OFF_AGG + (size_t)(bk >> 4)*NC + t] = bcv;
    }

    #pragma unroll
    for (int o = 16; o; o >>= 1) {
        s  += __shfl_xor_sync(0xffffffffu, s, o);
        sq += __shfl_xor_sync(0xffffffffu, sq, o);
    }
    if ((t & 31) == 0) { red[t >> 5] = s; red[8 + (t >> 5)] = sq; }
    __syncthreads();
    if (t == 0) {
        float S = 0.f, Q = 0.f;
        #pragma unroll
        for (int w = 0; w < 8; w++) { S += red[w]; Q += red[8 + w]; }
        float mu  = S * (1.f/ND);
        float var = Q * (1.f/ND) - mu*mu;
        stats[0] = mu; stats[1] = rsqrtf(var + 1e-6f);
    }
    __syncthreads();
    const float mu = stats[0], rs = stats[1];
    #pragma unroll
    for (int i = 0; i < 3; i++) {
        int d = t + i*256;
        out[OFF_VN + (size_t)bk*ND + d] = (v[i] - mu) * rs * gamma[d] + beta[d];
    }
}

// ---------------------------------------------------------------------------
// k2b: logits_parts[b,k,c] += vn[b,k,dchunk] @ w[dchunk,c]; agg folded in.
// Grid (16 dc, 32 b, 2 k-halves) = 1024 blocks; bias pre-seeded by k2a.
// ---------------------------------------------------------------------------
#define DCH 48
#define KH 8
__global__ __launch_bounds__(256, 4)
void k2b(const float* __restrict__ w, float* __restrict__ out)
{
    const int dc = blockIdx.x;            // 0..15
    const int b  = blockIdx.y;
    const int kh = blockIdx.z;            // 0..1 -> k in [kh*8, kh*8+8)
    const int t  = threadIdx.x;
    __shared__ u64 vn_s[KH*(DCH/2)];      // packed d-pairs (1.5 KB)

    const float* vn = out + OFF_VN + ((size_t)b*KF + kh*KH)*ND + dc*DCH;
    for (int i = t; i < KH*(DCH/2); i += 256) {
        int k = i / (DCH/2), dp = i - k*(DCH/2);
        float2 v = *(const float2*)&vn[(size_t)k*ND + 2*dp];
        vn_s[i] = pack2(v.x, v.y);
    }
    __syncthreads();

    if (t < NC) {
        const float* wp = w + (size_t)(dc*DCH)*NC + t;   // coalesced in c
        u64 acc[KH];
        #pragma unroll
        for (int k = 0; k < KH; k++) acc[k] = 0ULL;
        #pragma unroll
        for (int dp = 0; dp < DCH/2; dp++) {
            float w0 = __ldg(wp + (size_t)(2*dp)*NC);
            float w1 = __ldg(wp + (size_t)(2*dp + 1)*NC);
            u64 wv = pack2(w0, w1);
            #pragma unroll
            for (int k = 0; k < KH; k++)
                acc[k] = fma2(vn_s[k*(DCH/2) + dp], wv, acc[k]);
        }
        float* parts = out + OFF_PARTS + ((size_t)b*KF + kh*KH)*NC + t;
        float ssum = 0.f;
        #pragma unroll
        for (int k = 0; k < KH; k++) {
            float2 h = unpack2(acc[k]);
            float s = h.x + h.y;
            atomicAdd(parts + (size_t)k*NC, s);
            ssum += s;
        }
        atomicAdd(out + OFF_AGG + b*NC + t, ssum * (1.f/KF));
    }
}

// ---------------------------------------------------------------------------
extern "C" void kernel_launch(void* const* d_in, const int* in_sizes, int n_in,
                              void* d_out, int out_size)
{
    const float* x     = (const float*)d_in[0];  // (32,24,24,768)
    const float* proto = (const float*)d_in[1];  // (17,768)
    const float* gamma = (const float*)d_in[2];  // (768,)
    const float* beta  = (const float*)d_in[3];  // (768,)
    const float* w     = (const float*)d_in[4];  // (768,200)
    const float* bc    = (const float*)d_in[5];  // (200,)
    float* out = (float*)d_out;

    const size_t smem1 = (size_t)(TILE_P*XSP         // xs (padded)
                                + TILE_P*DSP         // dist_s
                                + TILE_P*KF          // a_c
                                + TILE_P             // a16
                                + KP1) * sizeof(float);  // ~209 KB
    cudaFuncSetAttribute(k1, cudaFuncAttributeMaxDynamicSharedMemorySize, (int)smem1);

    k1<<<dim3(NTILES, NB), T1, smem1>>>(x, proto, out);
    k2a<<<NB*KF, 256>>>(out, gamma, beta, bc);
    k2b<<<dim3(16, NB, 2), 256>>>(w, out);
}

// round 12
// speedup vs baseline: 1.1201x; 1.1201x over previous
#include <cuda_runtime.h>
#include <math_constants.h>

// Problem constants
#define NB 32
#define NP 576
#define ND 768
#define KP1 17
#define KF 16
#define NC 200
#define TILE_P 64
#define NTILES 9      // 576 / 64
#define T1 512

// Output layout: concatenation of (A, v_norm, logits_parts, logits_agg)
#define SZ_A (NB*KP1*NP)            // 313344
#define OFF_VN (SZ_A)
#define SZ_VN (NB*KF*ND)            // 393216
#define OFF_PARTS (OFF_VN + SZ_VN)
#define SZ_PARTS (NB*KF*NC)         // 102400
#define OFF_AGG (OFF_PARTS + SZ_PARTS)

typedef unsigned long long u64;

// Per-tile v partials: [tile 9][b 32][k 16][d 768], 14.2 MB.
// Fully rewritten by k1 each launch (no zero/clear invariant needed).
__device__ float g_vp[(size_t)NTILES*NB*KF*ND];

// ---- f32x2 helpers (k2b only — measured SLOWER than scalar in k1 loops) ----
__device__ __forceinline__ u64 fma2(u64 a, u64 b, u64 c) {
    u64 d; asm("fma.rn.f32x2 %0, %1, %2, %3;" : "=l"(d) : "l"(a), "l"(b), "l"(c));
    return d;
}
__device__ __forceinline__ u64 pack2(float lo, float hi) {
    u64 r; asm("mov.b64 %0, {%1,%2};" : "=l"(r) : "f"(lo), "f"(hi));
    return r;
}
__device__ __forceinline__ float2 unpack2(u64 v) {
    float2 r; asm("mov.b64 {%0,%1}, %2;" : "=f"(r.x), "=f"(r.y) : "l"(v));
    return r;
}

// ---------------------------------------------------------------------------
// k1: per (image, 64-patch tile) block. 512 threads, 1 block/SM (218 KB smem).
//  Staging pipelined by warp specialization (h0 all, h1 by warps 8-15).
//  Phase 1: scalar float4 dots, 4 patches/warp, 3-level shfl reduce, softmax.
//  Phase 2: 384 threads own d-pairs; epilogue is PLAIN float2 stores to the
//           per-tile partial buffer (no atomics). 128 threads write A.
// ---------------------------------------------------------------------------
__global__ __launch_bounds__(T1, 1)
void k1(const float* __restrict__ x,
        const float* __restrict__ proto,
        float* __restrict__ out)
{
    extern __shared__ float sm[];
    float* xs     = sm;                        // 64*768 floats (196.6 KB)
    float* a_part = xs + TILE_P*ND;            // 64*17*4 partials (17.4 KB)
    float* a_c    = a_part + TILE_P*KP1*4;     // 64*16 compact a (16B-aligned)
    float* a16    = a_c + TILE_P*KF;           // 64 (k=16 attention)
    float* psq    = a16 + TILE_P;              // 17

    const int t = threadIdx.x, warp = t >> 5, lane = t & 31;
    const int tile = blockIdx.x, b = blockIdx.y;

    float4* xs4 = (float4*)xs;
    const float4* xg = (const float4*)(x + ((size_t)b*NP + (size_t)tile*TILE_P)*ND);

    // --- stage HALF 0 (patches 0-31: 6144 float4) with all 512 threads ---
    #pragma unroll
    for (int i = 0; i < 12; i++)
        xs4[t + i*T1] = xg[t + i*T1];

    // --- per-block ||p_k||^2 (overlaps staging; proto L1/L2-resident) ---
    for (int k = warp; k < KP1; k += 16) {     // warp w: k=w; warp 0 also k=16
        const float4* pk = (const float4*)(proto + (size_t)k*ND);
        float s = 0.f;
        #pragma unroll
        for (int i = 0; i < 6; i++) {
            float4 v = __ldg(&pk[lane + 32*i]);
            s += v.x*v.x + v.y*v.y + v.z*v.z + v.w*v.w;
        }
        #pragma unroll
        for (int o = 16; o; o >>= 1) s += __shfl_xor_sync(0xffffffffu, s, o);
        if (lane == 0) psq[k] = s;
    }
    __syncthreads();    // h0 + psq visible

    // --- warps 8-15: stage HALF 1 (patches 32-63) before their dots ---
    if (warp >= 8) {
        const int tt = t - 256;
        #pragma unroll
        for (int i = 0; i < 24; i++)
            xs4[6144 + tt + i*256] = xg[6144 + tt + i*256];
        asm volatile("bar.sync 1, 256;" ::: "memory");   // warps 8-15 only
    }

    // --- Phase 1: scalar float4 dots, 4 patches per warp ---
    const int p0 = warp * 4;
    {
        float acc[4][KP1];
        #pragma unroll
        for (int p = 0; p < 4; p++)
            #pragma unroll
            for (int k = 0; k < KP1; k++) acc[p][k] = 0.f;

        const float4* pr4 = (const float4*)proto;
        #pragma unroll
        for (int j = 0; j < 6; j++) {
            float4 xv[4];
            #pragma unroll
            for (int p = 0; p < 4; p++) xv[p] = xs4[(p0 + p)*(ND/4) + j*32 + lane];
            #pragma unroll
            for (int k = 0; k < KP1; k++) {
                float4 pv = __ldg(&pr4[k*(ND/4) + j*32 + lane]);
                #pragma unroll
                for (int p = 0; p < 4; p++)
                    acc[p][k] += xv[p].x*pv.x + xv[p].y*pv.y
                               + xv[p].z*pv.z + xv[p].w*pv.w;
            }
        }

        // 3-level shfl reduce -> 4 partials per dot, lanes 0-3 store
        #pragma unroll
        for (int p = 0; p < 4; p++)
            #pragma unroll
            for (int k = 0; k < KP1; k++) {
                float v = acc[p][k];
                v += __shfl_xor_sync(0xffffffffu, v, 16);
                v += __shfl_xor_sync(0xffffffffu, v, 8);
                v += __shfl_xor_sync(0xffffffffu, v, 4);
                if (lane < 4) a_part[((p0 + p)*KP1 + k)*4 + lane] = v;
            }
    }
    __syncwarp();

    // --- lane-parallel softmax: softmax_k(2*xp - psq) == softmax(-dists) ---
    const float4* a_part4 = (const float4*)a_part;
    #pragma unroll
    for (int p = 0; p < 4; p++) {
        const int pl = p0 + p;
        float s = -CUDART_INF_F;
        if (lane < KP1) {
            float4 t4 = a_part4[pl*KP1 + lane];
            float dot = (t4.x + t4.y) + (t4.z + t4.w);
            s = fmaf(2.f, dot, -psq[lane]);
        }
        float m = s;
        #pragma unroll
        for (int o = 16; o; o >>= 1) m = fmaxf(m, __shfl_xor_sync(0xffffffffu, m, o));
        float e = (lane < KP1) ? __expf(s - m) : 0.f;
        float ssum = e;
        #pragma unroll
        for (int o = 16; o; o >>= 1) ssum += __shfl_xor_sync(0xffffffffu, ssum, o);
        float av = e * (1.f / ssum);
        if (lane < KF)       a_c[pl*KF + lane] = av;
        else if (lane == KF) a16[pl] = av;
    }
    __syncthreads();

    if (t >= 384) {
        // --- A output on the 128 spare threads: rows contiguous in p ---
        int tt = t - 384;
        #pragma unroll
        for (int i = tt; i < KP1*TILE_P; i += 128) {
            int k = i >> 6, p = i & 63;
            float av = (k < KF) ? a_c[p*KF + k] : a16[p];
            out[((size_t)b*KP1 + k)*NP + (size_t)tile*TILE_P + p] = av;
        }
    } else {
        // --- Phase 2: thread owns d-pair (2t, 2t+1); scalar FMA ---
        float2 vacc[KF];
        #pragma unroll
        for (int k = 0; k < KF; k++) { vacc[k].x = 0.f; vacc[k].y = 0.f; }
        const float2* xs2 = (const float2*)xs;
        const float4* ac4 = (const float4*)a_c;
        #pragma unroll 4
        for (int p = 0; p < TILE_P; p++) {
            float2 xv = xs2[p*(ND/2) + t];
            float4 a0 = ac4[p*4 + 0], a1 = ac4[p*4 + 1];   // broadcast LDS.128
            float4 a2 = ac4[p*4 + 2], a3 = ac4[p*4 + 3];
            const float av[KF] = { a0.x,a0.y,a0.z,a0.w, a1.x,a1.y,a1.z,a1.w,
                                   a2.x,a2.y,a2.z,a2.w, a3.x,a3.y,a3.z,a3.w };
            #pragma unroll
            for (int k = 0; k < KF; k++) {
                vacc[k].x += av[k] * xv.x;
                vacc[k].y += av[k] * xv.y;
            }
        }
        // PLAIN stores to per-tile partial slab — no atomics, no round-trip
        float2* vp2 = (float2*)(g_vp + (((size_t)tile*NB + b)*KF)*ND);
        #pragma unroll
        for (int k = 0; k < KF; k++)
            vp2[k*(ND/2) + t] = vacc[k];              // STG.64, coalesced
    }
}

// ---------------------------------------------------------------------------
// k2a: reduce the 9 tile-partials, LayerNorm over D for each (b,k), /P scale.
// Seeds parts/agg with the bias so k2b can use pure red.global.add.
// ---------------------------------------------------------------------------
__global__ __launch_bounds__(256, 4)
void k2a(float* __restrict__ out,
         const float* __restrict__ gamma, const float* __restrict__ beta,
         const float* __restrict__ b_cls)
{
    const int bk = blockIdx.x;            // b*16 + k
    const int t = threadIdx.x;
    __shared__ float red[16];
    __shared__ float stats[2];
    const float invP = 1.f / (float)NP;
    const size_t base = (size_t)bk*ND;    // (b*KF + k)*ND
    const size_t tstride = (size_t)NB*KF*ND;

    float v[3]; float s = 0.f, sq = 0.f;
    #pragma unroll
    for (int i = 0; i < 3; i++) {
        const int d = t + i*256;
        float val = 0.f;
        #pragma unroll
        for (int tile = 0; tile < NTILES; tile++)
            val += g_vp[(size_t)tile*tstride + base + d];   // 9 independent LDGs
        val *= invP;
        v[i] = val; s += val; sq += val*val;
    }

    // seed logits_parts / logits_agg with the classifier bias
    if (t < NC) {
        float bcv = b_cls[t];
        out[OFF_PARTS + (size_t)bk*NC + t] = bcv;
        if ((bk & 15) == 0) out[OFF_AGG + (size_t)(bk >> 4)*NC + t] = bcv;
    }

    #pragma unroll
    for (int o = 16; o; o >>= 1) {
        s  += __shfl_xor_sync(0xffffffffu, s, o);
        sq += __shfl_xor_sync(0xffffffffu, sq, o);
    }
    if ((t & 31) == 0) { red[t >> 5] = s; red[8 + (t >> 5)] = sq; }
    __syncthreads();
    if (t == 0) {
        float S = 0.f, Q = 0.f;
        #pragma unroll
        for (int w = 0; w < 8; w++) { S += red[w]; Q += red[8 + w]; }
        float mu  = S * (1.f/ND);
        float var = Q * (1.f/ND) - mu*mu;
        stats[0] = mu; stats[1] = rsqrtf(var + 1e-6f);
    }
    __syncthreads();
    const float mu = stats[0], rs = stats[1];
    #pragma unroll
    for (int i = 0; i < 3; i++) {
        int d = t + i*256;
        out[OFF_VN + (size_t)bk*ND + d] = (v[i] - mu) * rs * gamma[d] + beta[d];
    }
}

// ---------------------------------------------------------------------------
// k2b: logits_parts[b,k,c] += vn[b,k,dchunk] @ w[dchunk,c]; agg folded in.
// Grid (16 dc, 32 b, 2 k-halves) = 1024 blocks; bias pre-seeded by k2a.
// ---------------------------------------------------------------------------
#define DCH 48
#define KH 8
__global__ __launch_bounds__(256, 4)
void k2b(const float* __restrict__ w, float* __restrict__ out)
{
    const int dc = blockIdx.x;            // 0..15
    const int b  = blockIdx.y;
    const int kh = blockIdx.z;            // 0..1 -> k in [kh*8, kh*8+8)
    const int t  = threadIdx.x;
    __shared__ u64 vn_s[KH*(DCH/2)];      // packed d-pairs (1.5 KB)

    const float* vn = out + OFF_VN + ((size_t)b*KF + kh*KH)*ND + dc*DCH;
    for (int i = t; i < KH*(DCH/2); i += 256) {
        int k = i / (DCH/2), dp = i - k*(DCH/2);
        float2 v = *(const float2*)&vn[(size_t)k*ND + 2*dp];
        vn_s[i] = pack2(v.x, v.y);
    }
    __syncthreads();

    if (t < NC) {
        const float* wp = w + (size_t)(dc*DCH)*NC + t;   // coalesced in c
        u64 acc[KH];
        #pragma unroll
        for (int k = 0; k < KH; k++) acc[k] = 0ULL;
        #pragma unroll
        for (int dp = 0; dp < DCH/2; dp++) {
            float w0 = __ldg(wp + (size_t)(2*dp)*NC);
            float w1 = __ldg(wp + (size_t)(2*dp + 1)*NC);
            u64 wv = pack2(w0, w1);
            #pragma unroll
            for (int k = 0; k < KH; k++)
                acc[k] = fma2(vn_s[k*(DCH/2) + dp], wv, acc[k]);
        }
        float* parts = out + OFF_PARTS + ((size_t)b*KF + kh*KH)*NC + t;
        float ssum = 0.f;
        #pragma unroll
        for (int k = 0; k < KH; k++) {
            float2 h = unpack2(acc[k]);
            float s = h.x + h.y;
            atomicAdd(parts + (size_t)k*NC, s);
            ssum += s;
        }
        atomicAdd(out + OFF_AGG + b*NC + t, ssum * (1.f/KF));
    }
}

// ---------------------------------------------------------------------------
extern "C" void kernel_launch(void* const* d_in, const int* in_sizes, int n_in,
                              void* d_out, int out_size)
{
    const float* x     = (const float*)d_in[0];  // (32,24,24,768)
    const float* proto = (const float*)d_in[1];  // (17,768)
    const float* gamma = (const float*)d_in[2];  // (768,)
    const float* beta  = (const float*)d_in[3];  // (768,)
    const float* w     = (const float*)d_in[4];  // (768,200)
    const float* bc    = (const float*)d_in[5];  // (200,)
    float* out = (float*)d_out;

    const size_t smem1 = (size_t)(TILE_P*ND          // xs
                                + TILE_P*KP1*4       // a_part
                                + TILE_P*KF          // a_c
                                + TILE_P             // a16
                                + KP1) * sizeof(float);  // ~218.4 KB
    cudaFuncSetAttribute(k1, cudaFuncAttributeMaxDynamicSharedMemorySize, (int)smem1);

    k1<<<dim3(NTILES, NB), T1, smem1>>>(x, proto, out);
    k2a<<<NB*KF, 256>>>(out, gamma, beta, bc);
    k2b<<<dim3(16, NB, 2), 256>>>(w, out);
}